// round 2
// baseline (speedup 1.0000x reference)
#include <cuda_runtime.h>
#include <cstdint>
#include <math_constants.h>

#define B_ 32
#define S_ 2048
#define H_ 1024

// Scratch (no device allocation allowed)
__device__ float g_qadd[B_ * H_];     // Wa_b + Ua_b + query @ Wa^T   [B,H]
__device__ float g_scores[B_ * S_];   // pre-softmax scores           [B,S]

__device__ __forceinline__ float tanh_fast(float x) {
    float y;
    asm("tanh.approx.f32 %0, %1;" : "=f"(y) : "f"(x));
    return y;
}

// ---------------------------------------------------------------------------
// K1: qadd[b][g] = Wa_b[g] + Ua_b[g] + sum_h query[b][h] * Wa_w[g][h]
// grid=32 (one per b), block=256. Warp-per-output with coalesced Wa_w rows.
// ---------------------------------------------------------------------------
__global__ void k1_qproj(const float* __restrict__ query,
                         const float* __restrict__ Wa_w,
                         const float* __restrict__ Wa_b,
                         const float* __restrict__ Ua_b) {
    int b = blockIdx.x;
    __shared__ float q_s[H_];
    for (int i = threadIdx.x; i < H_; i += blockDim.x)
        q_s[i] = query[b * H_ + i];
    __syncthreads();

    int warp = threadIdx.x >> 5;
    int lane = threadIdx.x & 31;
    for (int gi = 0; gi < 128; gi++) {
        int g = warp * 128 + gi;
        const float* wrow = Wa_w + (size_t)g * H_;
        float acc = 0.f;
        #pragma unroll 8
        for (int h = lane; h < H_; h += 32)
            acc += q_s[h] * wrow[h];
        #pragma unroll
        for (int off = 16; off; off >>= 1)
            acc += __shfl_xor_sync(0xffffffffu, acc, off);
        if (lane == 0)
            g_qadd[b * H_ + g] = acc + Wa_b[g] + Ua_b[g];
    }
}

// ---------------------------------------------------------------------------
// K2: fused scores GEMM.
//   score[b,s] = Va_b + sum_g Va[g] * tanh(qadd[b][g] + sum_h keys[b,s,h]*Ua[g][h])
// mma.sync.m16n8k8 tf32. CTA tile: M=128 rows x N=128 features, TK=32.
// 8 warps: wm = wid>>1 (4 row strips of 32), wn = wid&1 (2 col strips of 64).
// Warp tile 32x64 = 2(m) x 8(n) mma tiles. Accumulators live across full K,
// per N-tile epilogue folds tanh + Va into per-row score partials.
// ---------------------------------------------------------------------------
#define TM 128
#define TN 128
#define TK 32
#define SPAD 36   // stride so frag loads hit bank 4*grp+qid: conflict-free

__global__ __launch_bounds__(256) void k2_scores(
    const float* __restrict__ keys,
    const float* __restrict__ Ua_w,
    const float* __restrict__ Va_w,
    const float* __restrict__ Va_b) {

    __shared__ float a_s[TM][SPAD];   // keys tile  [m][k]
    __shared__ float b_s[TN][SPAD];   // Ua tile    [n][k]
    __shared__ float qv_s[TN];
    __shared__ float va_s[TN];
    __shared__ float sc_s[TM];

    int tid  = threadIdx.x;
    int wid  = tid >> 5;
    int lane = tid & 31;
    int wm   = wid >> 1;          // 0..3
    int wn   = wid & 1;           // 0..1
    int grp  = lane >> 2;         // 0..7
    int qid  = lane & 3;          // 0..3

    int blk = blockIdx.x;
    int b   = blk >> 4;                 // 16 s-tiles per batch
    int s0  = (blk & 15) * TM;
    const float* keys_blk = keys + ((size_t)b * S_ + s0) * H_;

    if (tid < TM) sc_s[tid] = 0.f;

    float part[4] = {0.f, 0.f, 0.f, 0.f};   // [mi*2 + rowhalf]

    for (int nt = 0; nt < H_ / TN; nt++) {
        __syncthreads();   // previous epilogue reads done before re-staging
        if (tid < TN) {
            qv_s[tid] = g_qadd[b * H_ + nt * TN + tid];
            va_s[tid] = Va_w[nt * TN + tid];
        }

        float acc[2][8][4];
        #pragma unroll
        for (int mi = 0; mi < 2; mi++)
            #pragma unroll
            for (int ni = 0; ni < 8; ni++)
                #pragma unroll
                for (int c = 0; c < 4; c++)
                    acc[mi][ni][c] = 0.f;

        for (int kt = 0; kt < H_ / TK; kt++) {
            __syncthreads();
            // Stage A (keys) and B (Ua) tiles: 128 rows x 32 floats each.
            // 8 threads per row -> fully coalesced 128B row segments.
            {
                int rr = tid >> 3;        // 0..31
                int c4 = tid & 7;         // float4 index 0..7
                #pragma unroll
                for (int p = 0; p < 4; p++) {
                    int r = p * 32 + rr;
                    float4 va4 = *(const float4*)(keys_blk + (size_t)r * H_ + kt * TK + c4 * 4);
                    *(float4*)&a_s[r][c4 * 4] = va4;
                    float4 vb4 = *(const float4*)(Ua_w + (size_t)(nt * TN + r) * H_ + kt * TK + c4 * 4);
                    *(float4*)&b_s[r][c4 * 4] = vb4;
                }
            }
            __syncthreads();

            #pragma unroll
            for (int k8 = 0; k8 < TK / 8; k8++) {
                int kb = k8 * 8;
                uint32_t af[2][4];
                uint32_t bf[8][2];
                #pragma unroll
                for (int mi = 0; mi < 2; mi++) {
                    int r = wm * 32 + mi * 16;
                    af[mi][0] = __float_as_uint(a_s[r + grp    ][kb + qid    ]);
                    af[mi][1] = __float_as_uint(a_s[r + grp + 8][kb + qid    ]);
                    af[mi][2] = __float_as_uint(a_s[r + grp    ][kb + qid + 4]);
                    af[mi][3] = __float_as_uint(a_s[r + grp + 8][kb + qid + 4]);
                }
                #pragma unroll
                for (int ni = 0; ni < 8; ni++) {
                    int n = wn * 64 + ni * 8;
                    bf[ni][0] = __float_as_uint(b_s[n + grp][kb + qid    ]);
                    bf[ni][1] = __float_as_uint(b_s[n + grp][kb + qid + 4]);
                }
                #pragma unroll
                for (int mi = 0; mi < 2; mi++)
                    #pragma unroll
                    for (int ni = 0; ni < 8; ni++) {
                        asm volatile(
                            "mma.sync.aligned.m16n8k8.row.col.f32.tf32.tf32.f32 "
                            "{%0,%1,%2,%3}, {%4,%5,%6,%7}, {%8,%9}, {%0,%1,%2,%3};\n"
                            : "+f"(acc[mi][ni][0]), "+f"(acc[mi][ni][1]),
                              "+f"(acc[mi][ni][2]), "+f"(acc[mi][ni][3])
                            : "r"(af[mi][0]), "r"(af[mi][1]),
                              "r"(af[mi][2]), "r"(af[mi][3]),
                              "r"(bf[ni][0]), "r"(bf[ni][1]));
                    }
            }
        }

        // Epilogue for this N-tile: tanh + Va fold into row partials.
        #pragma unroll
        for (int ni = 0; ni < 8; ni++) {
            #pragma unroll
            for (int c = 0; c < 4; c++) {
                int gl = wn * 64 + ni * 8 + qid * 2 + (c & 1);
                float qv = qv_s[gl];
                float va = va_s[gl];
                #pragma unroll
                for (int mi = 0; mi < 2; mi++) {
                    float t = tanh_fast(qv + acc[mi][ni][c]);
                    part[mi * 2 + (c >> 1)] += va * t;
                }
            }
        }
    }

    // Reduce over the 4 lanes (qid) that share each row.
    #pragma unroll
    for (int i = 0; i < 4; i++) {
        part[i] += __shfl_xor_sync(0xffffffffu, part[i], 1);
        part[i] += __shfl_xor_sync(0xffffffffu, part[i], 2);
    }
    if (qid == 0) {
        #pragma unroll
        for (int mi = 0; mi < 2; mi++)
            #pragma unroll
            for (int h = 0; h < 2; h++)
                atomicAdd(&sc_s[wm * 32 + mi * 16 + h * 8 + grp], part[mi * 2 + h]);
    }
    __syncthreads();
    if (tid < TM)
        g_scores[b * S_ + s0 + tid] = sc_s[tid] + Va_b[0];
}

// ---------------------------------------------------------------------------
// K3: softmax over S per batch row. grid=32, block=256 (8 elems/thread).
// ---------------------------------------------------------------------------
__global__ void k3_softmax(float* __restrict__ out_w) {
    int b = blockIdx.x;
    int tid = threadIdx.x;
    const float* sc = g_scores + b * S_;
    __shared__ float red_max[8];
    __shared__ float red_sum[8];

    float v[8];
    float lmax = -CUDART_INF_F;
    #pragma unroll
    for (int i = 0; i < 8; i++) {
        v[i] = sc[tid + i * 256];
        lmax = fmaxf(lmax, v[i]);
    }
    #pragma unroll
    for (int o = 16; o; o >>= 1)
        lmax = fmaxf(lmax, __shfl_xor_sync(0xffffffffu, lmax, o));
    if ((tid & 31) == 0) red_max[tid >> 5] = lmax;
    __syncthreads();
    float m = red_max[0];
    #pragma unroll
    for (int w = 1; w < 8; w++) m = fmaxf(m, red_max[w]);

    float lsum = 0.f;
    #pragma unroll
    for (int i = 0; i < 8; i++) {
        v[i] = __expf(v[i] - m);
        lsum += v[i];
    }
    #pragma unroll
    for (int o = 16; o; o >>= 1)
        lsum += __shfl_xor_sync(0xffffffffu, lsum, o);
    if ((tid & 31) == 0) red_sum[tid >> 5] = lsum;
    __syncthreads();
    float s = 0.f;
    #pragma unroll
    for (int w = 0; w < 8; w++) s += red_sum[w];
    float inv = 1.f / s;
    #pragma unroll
    for (int i = 0; i < 8; i++)
        out_w[b * S_ + tid + i * 256] = v[i] * inv;
}

// ---------------------------------------------------------------------------
// K4: context[b][h] = sum_s w[b][s] * keys[b][s][h].
// grid = 32*4 (b, 256-wide h chunks), block=256. Coalesced keys columns,
// weights staged in smem, unroll-8 for MLP.
// ---------------------------------------------------------------------------
__global__ void k4_context(const float* __restrict__ keys,
                           const float* __restrict__ w,
                           float* __restrict__ ctx) {
    int b  = blockIdx.x >> 2;
    int h  = ((blockIdx.x & 3) * 256) + threadIdx.x;
    __shared__ float w_s[S_];
    for (int i = threadIdx.x; i < S_; i += 256)
        w_s[i] = w[b * S_ + i];
    __syncthreads();

    const float* kb = keys + (size_t)b * S_ * H_ + h;
    float acc = 0.f;
    #pragma unroll 8
    for (int s = 0; s < S_; s++)
        acc += w_s[s] * kb[(size_t)s * H_];
    ctx[b * H_ + h] = acc;
}

// ---------------------------------------------------------------------------
// Launch: outputs are (context[32,1,1024], weights[32,2048]) flattened:
//   d_out[0      .. 32767] = context
//   d_out[32768 .. 98303] = weights
// ---------------------------------------------------------------------------
extern "C" void kernel_launch(void* const* d_in, const int* in_sizes, int n_in,
                              void* d_out, int out_size) {
    const float* query = (const float*)d_in[0];
    const float* keys  = (const float*)d_in[1];
    const float* Wa_w  = (const float*)d_in[2];
    const float* Wa_b  = (const float*)d_in[3];
    const float* Ua_w  = (const float*)d_in[4];
    const float* Ua_b  = (const float*)d_in[5];
    const float* Va_w  = (const float*)d_in[6];
    const float* Va_b  = (const float*)d_in[7];

    float* ctx  = (float*)d_out;
    float* wout = ctx + B_ * H_;

    k1_qproj<<<B_, 256>>>(query, Wa_w, Wa_b, Ua_b);
    k2_scores<<<(B_ * S_) / TM, 256>>>(keys, Ua_w, Va_w, Va_b);
    k3_softmax<<<B_, 256>>>(wout);
    k4_context<<<B_ * 4, 256>>>(keys, wout, ctx);
}

// round 5
// speedup vs baseline: 1.4583x; 1.4583x over previous
#include <cuda_runtime.h>
#include <cstdint>
#include <math_constants.h>

#define B_ 32
#define S_ 2048
#define H_ 1024

// Scratch (no device allocation allowed)
__device__ float g_qadd[B_ * H_];          // Wa_b + Ua_b + query @ Wa^T   [B,H]
__device__ float g_scores[B_ * S_];        // pre-softmax scores           [B,S]
__device__ float g_ctxp[16 * B_ * H_];     // K4 split-S partials (deterministic)

__device__ __forceinline__ float tanh_fast(float x) {
    float y;
    asm("tanh.approx.f32 %0, %1;" : "=f"(y) : "f"(x));
    return y;
}

__device__ __forceinline__ uint32_t smem_u32(const void* p) {
    uint32_t a;
    asm("{ .reg .u64 t; cvta.to.shared.u64 t, %1; cvt.u32.u64 %0, t; }" : "=r"(a) : "l"(p));
    return a;
}

// ---------------------------------------------------------------------------
// K1: qadd[b][g] = Wa_b[g] + Ua_b[g] + sum_h query[b][h] * Wa_w[g][h]
// grid=(32,8), block=256. Each warp: 16 outputs, coalesced Wa rows.
// ---------------------------------------------------------------------------
__global__ void k1_qproj(const float* __restrict__ query,
                         const float* __restrict__ Wa_w,
                         const float* __restrict__ Wa_b,
                         const float* __restrict__ Ua_b) {
    int b = blockIdx.x;
    int g0 = blockIdx.y * 128;
    __shared__ float q_s[H_];
    for (int i = threadIdx.x; i < H_; i += blockDim.x)
        q_s[i] = query[b * H_ + i];
    __syncthreads();

    int warp = threadIdx.x >> 5;
    int lane = threadIdx.x & 31;
    for (int gi = 0; gi < 16; gi++) {
        int g = g0 + warp * 16 + gi;
        const float* wrow = Wa_w + (size_t)g * H_;
        float acc = 0.f;
        #pragma unroll 8
        for (int h = lane; h < H_; h += 32)
            acc += q_s[h] * wrow[h];
        #pragma unroll
        for (int off = 16; off; off >>= 1)
            acc += __shfl_xor_sync(0xffffffffu, acc, off);
        if (lane == 0)
            g_qadd[b * H_ + g] = acc + Wa_b[g] + Ua_b[g];
    }
}

// ---------------------------------------------------------------------------
// K2: fused scores GEMM via mma.sync.m16n8k8 tf32, cp.async double-buffered.
//   score[b,s] = Va_b + sum_g Va[g]*tanh(qadd[b][g] + sum_h keys[b,s,h]*Ua[g][h])
// CTA tile M=128 x N=128, TK=32. 8 warps: wm=wid>>1 (4 row strips of 32),
// wn=wid&1 (2 col strips of 64). Warp tile 32x64 = 2(m) x 8(n) mma tiles.
// Pipeline per kt: wait_group 0 -> 1 syncthreads -> cp.async(kt+1) -> frags+mma(kt).
// ---------------------------------------------------------------------------
#define TM 128
#define TN 128
#define TK 32
#define SPAD 36                        // frag LDS bank = 4*grp+qid: conflict-free
#define ABYTES (TM * SPAD * 4)         // 18432
// dynamic smem byte offsets
#define SM_SC  0                       // 128 floats
#define SM_QV  512                     // 128 floats
#define SM_VA  1024                    // 128 floats
#define SM_A   1536                    // 2 buffers x 18432
#define SM_B   (SM_A + 2 * ABYTES)     // 2 buffers x 18432
#define SM_TOTAL (SM_B + 2 * ABYTES)   // 75264

__device__ __forceinline__ void cp16(uint32_t dst, const void* src) {
    asm volatile("cp.async.cg.shared.global [%0], [%1], 16;" :: "r"(dst), "l"(src));
}

// 256 threads stage one 128x32-float tile (8 float4 per row): 4 cp.async/thread.
__device__ __forceinline__ void stage_tile(const float* __restrict__ src,
                                           size_t row_stride, int kt, uint32_t buf) {
    int tid = threadIdx.x;
    #pragma unroll
    for (int i = 0; i < 4; i++) {
        int idx = i * 256 + tid;
        int row = idx >> 3, c = idx & 7;
        cp16(buf + (uint32_t)(row * (SPAD * 4) + c * 16),
             src + (size_t)row * row_stride + kt * TK + c * 4);
    }
}

__global__ __launch_bounds__(256, 2) void k2_scores(
    const float* __restrict__ keys,
    const float* __restrict__ Ua_w,
    const float* __restrict__ Va_w,
    const float* __restrict__ Va_b) {

    extern __shared__ char smem[];
    uint32_t sb = smem_u32(smem);
    float* sc_s = (float*)(smem + SM_SC);
    float* qv_s = (float*)(smem + SM_QV);
    float* va_s = (float*)(smem + SM_VA);

    int tid  = threadIdx.x;
    int wid  = tid >> 5;
    int lane = tid & 31;
    int wm   = wid >> 1;          // 0..3
    int wn   = wid & 1;           // 0..1
    int grp  = lane >> 2;         // 0..7
    int qid  = lane & 3;          // 0..3

    int blk = blockIdx.x;
    int b   = blk >> 4;
    int s0  = (blk & 15) * TM;
    const float* keys_blk = keys + ((size_t)b * S_ + s0) * H_;

    if (tid < TM) sc_s[tid] = 0.f;

    float part[4] = {0.f, 0.f, 0.f, 0.f};

    for (int nt = 0; nt < H_ / TN; nt++) {
        __syncthreads();   // prev epilogue qv_s/va_s reads done; prev frag reads done
        if (tid < TN) {
            qv_s[tid] = g_qadd[b * H_ + nt * TN + tid];
            va_s[tid] = Va_w[nt * TN + tid];
        }
        const float* Ua_nt = Ua_w + (size_t)(nt * TN) * H_;

        // prologue: stage chunk 0 into buffer 0
        stage_tile(keys_blk, H_, 0, sb + SM_A);
        stage_tile(Ua_nt,    H_, 0, sb + SM_B);
        asm volatile("cp.async.commit_group;" ::: "memory");

        float acc[2][8][4];
        #pragma unroll
        for (int mi = 0; mi < 2; mi++)
            #pragma unroll
            for (int ni = 0; ni < 8; ni++)
                #pragma unroll
                for (int c = 0; c < 4; c++)
                    acc[mi][ni][c] = 0.f;

        for (int kt = 0; kt < H_ / TK; kt++) {
            int cur = kt & 1;
            int nxt = cur ^ 1;

            asm volatile("cp.async.wait_group 0;" ::: "memory");
            __syncthreads();   // chunk kt visible to all; all frag reads of buf nxt done

            if (kt + 1 < H_ / TK) {
                stage_tile(keys_blk, H_, kt + 1, sb + SM_A + nxt * ABYTES);
                stage_tile(Ua_nt,    H_, kt + 1, sb + SM_B + nxt * ABYTES);
                asm volatile("cp.async.commit_group;" ::: "memory");
            }

            const float* a_s = (const float*)(smem + SM_A + cur * ABYTES);
            const float* b_s = (const float*)(smem + SM_B + cur * ABYTES);

            #pragma unroll
            for (int k8 = 0; k8 < TK / 8; k8++) {
                int kb = k8 * 8;
                uint32_t af[2][4];
                uint32_t bf[8][2];
                #pragma unroll
                for (int mi = 0; mi < 2; mi++) {
                    int r = wm * 32 + mi * 16;
                    af[mi][0] = __float_as_uint(a_s[(r + grp    ) * SPAD + kb + qid    ]);
                    af[mi][1] = __float_as_uint(a_s[(r + grp + 8) * SPAD + kb + qid    ]);
                    af[mi][2] = __float_as_uint(a_s[(r + grp    ) * SPAD + kb + qid + 4]);
                    af[mi][3] = __float_as_uint(a_s[(r + grp + 8) * SPAD + kb + qid + 4]);
                }
                #pragma unroll
                for (int ni = 0; ni < 8; ni++) {
                    int n = wn * 64 + ni * 8;
                    bf[ni][0] = __float_as_uint(b_s[(n + grp) * SPAD + kb + qid    ]);
                    bf[ni][1] = __float_as_uint(b_s[(n + grp) * SPAD + kb + qid + 4]);
                }
                #pragma unroll
                for (int mi = 0; mi < 2; mi++)
                    #pragma unroll
                    for (int ni = 0; ni < 8; ni++) {
                        asm volatile(
                            "mma.sync.aligned.m16n8k8.row.col.f32.tf32.tf32.f32 "
                            "{%0,%1,%2,%3}, {%4,%5,%6,%7}, {%8,%9}, {%0,%1,%2,%3};\n"
                            : "+f"(acc[mi][ni][0]), "+f"(acc[mi][ni][1]),
                              "+f"(acc[mi][ni][2]), "+f"(acc[mi][ni][3])
                            : "r"(af[mi][0]), "r"(af[mi][1]),
                              "r"(af[mi][2]), "r"(af[mi][3]),
                              "r"(bf[ni][0]), "r"(bf[ni][1]));
                    }
            }
        }

        // Epilogue: tanh + Va fold into per-row partials.
        #pragma unroll
        for (int ni = 0; ni < 8; ni++) {
            #pragma unroll
            for (int c = 0; c < 4; c++) {
                int gl = wn * 64 + ni * 8 + qid * 2 + (c & 1);
                float qv = qv_s[gl];
                float va = va_s[gl];
                #pragma unroll
                for (int mi = 0; mi < 2; mi++) {
                    float t = tanh_fast(qv + acc[mi][ni][c]);
                    part[mi * 2 + (c >> 1)] += va * t;
                }
            }
        }
    }

    // Reduce over the 4 lanes (qid) sharing each row.
    #pragma unroll
    for (int i = 0; i < 4; i++) {
        part[i] += __shfl_xor_sync(0xffffffffu, part[i], 1);
        part[i] += __shfl_xor_sync(0xffffffffu, part[i], 2);
    }
    if (qid == 0) {
        #pragma unroll
        for (int mi = 0; mi < 2; mi++)
            #pragma unroll
            for (int h = 0; h < 2; h++)
                atomicAdd(&sc_s[wm * 32 + mi * 16 + h * 8 + grp], part[mi * 2 + h]);
    }
    __syncthreads();
    if (tid < TM)
        g_scores[b * S_ + s0 + tid] = sc_s[tid] + Va_b[0];
}

// ---------------------------------------------------------------------------
// K3: softmax over S per batch row. grid=32, block=256 (8 elems/thread).
// ---------------------------------------------------------------------------
__global__ void k3_softmax(float* __restrict__ out_w) {
    int b = blockIdx.x;
    int tid = threadIdx.x;
    const float* sc = g_scores + b * S_;
    __shared__ float red_max[8];
    __shared__ float red_sum[8];

    float v[8];
    float lmax = -CUDART_INF_F;
    #pragma unroll
    for (int i = 0; i < 8; i++) {
        v[i] = sc[tid + i * 256];
        lmax = fmaxf(lmax, v[i]);
    }
    #pragma unroll
    for (int o = 16; o; o >>= 1)
        lmax = fmaxf(lmax, __shfl_xor_sync(0xffffffffu, lmax, o));
    if ((tid & 31) == 0) red_max[tid >> 5] = lmax;
    __syncthreads();
    float m = red_max[0];
    #pragma unroll
    for (int w = 1; w < 8; w++) m = fmaxf(m, red_max[w]);

    float lsum = 0.f;
    #pragma unroll
    for (int i = 0; i < 8; i++) {
        v[i] = __expf(v[i] - m);
        lsum += v[i];
    }
    #pragma unroll
    for (int o = 16; o; o >>= 1)
        lsum += __shfl_xor_sync(0xffffffffu, lsum, o);
    if ((tid & 31) == 0) red_sum[tid >> 5] = lsum;
    __syncthreads();
    float s = 0.f;
    #pragma unroll
    for (int w = 0; w < 8; w++) s += red_sum[w];
    float inv = 1.f / s;
    #pragma unroll
    for (int i = 0; i < 8; i++)
        out_w[b * S_ + tid + i * 256] = v[i] * inv;
}

// ---------------------------------------------------------------------------
// K4: split-S context partials, float4 columns.
// grid = 32*16 (b, s-chunk of 128), block=256: thread t owns cols 4t..4t+3.
//   g_ctxp[sc][b][:] = sum_{s in chunk} w[b][s] * keys[b][s][:]
// Deterministic; K5 reduces 16 partials.
// ---------------------------------------------------------------------------
__global__ void k4_context(const float* __restrict__ keys,
                           const float* __restrict__ w) {
    int bx = blockIdx.x;
    int b  = bx >> 4;
    int sc = bx & 15;

    __shared__ float w_s[128];
    if (threadIdx.x < 128)
        w_s[threadIdx.x] = w[b * S_ + sc * 128 + threadIdx.x];
    __syncthreads();

    const float4* kb = (const float4*)(keys + ((size_t)b * S_ + sc * 128) * H_) + threadIdx.x;
    float4 acc = make_float4(0.f, 0.f, 0.f, 0.f);
    #pragma unroll 8
    for (int s = 0; s < 128; s++) {
        float4 k4 = kb[(size_t)s * (H_ / 4)];
        float ws = w_s[s];
        acc.x += ws * k4.x;
        acc.y += ws * k4.y;
        acc.z += ws * k4.z;
        acc.w += ws * k4.w;
    }
    ((float4*)(g_ctxp + (size_t)sc * (B_ * H_) + b * H_))[threadIdx.x] = acc;
}

__global__ void k5_reduce(float* __restrict__ ctx) {
    int idx = blockIdx.x * 256 + threadIdx.x;
    float a = 0.f;
    #pragma unroll
    for (int p = 0; p < 16; p++)
        a += g_ctxp[p * (B_ * H_) + idx];
    ctx[idx] = a;
}

// ---------------------------------------------------------------------------
// Launch: d_out[0..32767] = context [32,1,1024]; d_out[32768..98303] = weights.
// ---------------------------------------------------------------------------
extern "C" void kernel_launch(void* const* d_in, const int* in_sizes, int n_in,
                              void* d_out, int out_size) {
    const float* query = (const float*)d_in[0];
    const float* keys  = (const float*)d_in[1];
    const float* Wa_w  = (const float*)d_in[2];
    const float* Wa_b  = (const float*)d_in[3];
    const float* Ua_w  = (const float*)d_in[4];
    const float* Ua_b  = (const float*)d_in[5];
    const float* Va_w  = (const float*)d_in[6];
    const float* Va_b  = (const float*)d_in[7];

    float* ctx  = (float*)d_out;
    float* wout = ctx + B_ * H_;

    static int smem_set = 0;
    if (!smem_set) {
        cudaFuncSetAttribute(k2_scores, cudaFuncAttributeMaxDynamicSharedMemorySize, SM_TOTAL);
        smem_set = 1;
    }

    k1_qproj<<<dim3(32, 8), 256>>>(query, Wa_w, Wa_b, Ua_b);
    k2_scores<<<(B_ * S_) / TM, 256, SM_TOTAL>>>(keys, Ua_w, Va_w, Va_b);
    k3_softmax<<<B_, 256>>>(wout);
    k4_context<<<B_ * 16, 256>>>(keys, wout);
    k5_reduce<<<(B_ * H_) / 256, 256>>>(ctx);
}

// round 8
// speedup vs baseline: 2.0971x; 1.4380x over previous
#include <cuda_runtime.h>
#include <cuda_fp16.h>
#include <cstdint>
#include <math_constants.h>

#define B_ 32
#define S_ 2048
#define H_ 1024

// Scratch (no device allocation allowed)
__device__ float  g_qadd[B_ * H_];          // Wa_b + Ua_b + query @ Wa^T   [B,H]
__device__ float  g_scores[B_ * S_];        // pre-softmax scores           [B,S]
__device__ float  g_ctxp[16 * B_ * H_];     // K4 split-S partials
__device__ __half g_keys_h[B_ * S_ * H_];   // fp16 copy of keys (134 MB)
__device__ __half g_Ua_h[H_ * H_];          // fp16 copy of Ua   (2 MB)

__device__ __forceinline__ float tanh_fast(float x) {
    float y;
    asm("tanh.approx.f32 %0, %1;" : "=f"(y) : "f"(x));
    return y;
}

__device__ __forceinline__ uint32_t smem_u32(const void* p) {
    uint32_t a;
    asm("{ .reg .u64 t; cvta.to.shared.u64 t, %1; cvt.u32.u64 %0, t; }" : "=r"(a) : "l"(p));
    return a;
}

// ---------------------------------------------------------------------------
// K0: fp32 -> fp16 conversion (8 elements / thread, 16B stores).
// ---------------------------------------------------------------------------
__global__ void k0_cvt(const float* __restrict__ src, __half* __restrict__ dst) {
    int i = (blockIdx.x * 256 + threadIdx.x) * 8;
    float4 f0 = *(const float4*)(src + i);
    float4 f1 = *(const float4*)(src + i + 4);
    __half2 h[4];
    h[0] = __floats2half2_rn(f0.x, f0.y);
    h[1] = __floats2half2_rn(f0.z, f0.w);
    h[2] = __floats2half2_rn(f1.x, f1.y);
    h[3] = __floats2half2_rn(f1.z, f1.w);
    *(uint4*)(dst + i) = *(uint4*)h;
}

// ---------------------------------------------------------------------------
// K1: qadd[b][g] = Wa_b[g] + Ua_b[g] + sum_h query[b][h] * Wa_w[g][h]
// ---------------------------------------------------------------------------
__global__ void k1_qproj(const float* __restrict__ query,
                         const float* __restrict__ Wa_w,
                         const float* __restrict__ Wa_b,
                         const float* __restrict__ Ua_b) {
    int b = blockIdx.x;
    int g0 = blockIdx.y * 128;
    __shared__ float q_s[H_];
    for (int i = threadIdx.x; i < H_; i += blockDim.x)
        q_s[i] = query[b * H_ + i];
    __syncthreads();

    int warp = threadIdx.x >> 5;
    int lane = threadIdx.x & 31;
    for (int gi = 0; gi < 16; gi++) {
        int g = g0 + warp * 16 + gi;
        const float* wrow = Wa_w + (size_t)g * H_;
        float acc = 0.f;
        #pragma unroll 8
        for (int h = lane; h < H_; h += 32)
            acc += q_s[h] * wrow[h];
        #pragma unroll
        for (int off = 16; off; off >>= 1)
            acc += __shfl_xor_sync(0xffffffffu, acc, off);
        if (lane == 0)
            g_qadd[b * H_ + g] = acc + Wa_b[g] + Ua_b[g];
    }
}

// ---------------------------------------------------------------------------
// K2: fused scores GEMM via mma.sync.m16n8k16.f16 (fp32 accum), fp16 operands
// pre-converted by K0 (fp16 mantissa == tf32 mantissa -> same accuracy).
// CTA tile M=128 x N=128, TK=32 halves/chunk (2 k16 steps), 3-stage cp.async.
// 8 warps: wm=wid>>1 (4 row strips of 32), wn=wid&1 (2 col strips of 64).
// Row pitch 40 halves (80B): frag LDS word = 20*grp + qid -> all 32 lanes
// distinct mod 32, conflict-free.
// ---------------------------------------------------------------------------
#define TM 128
#define TN 128
#define TK 32                          // halves per k-chunk
#define SPADH 40                       // halves per row (80 B pitch)
#define TILE_B (TM * SPADH * 2)        // 10240 bytes per tile
// dynamic smem byte offsets
#define SM_SC  0                       // 128 floats
#define SM_QV  512                     // 128 floats
#define SM_VA  1024                    // 128 floats
#define SM_A   1536                    // 3 buffers x 10240
#define SM_B   (SM_A + 3 * TILE_B)
#define SM_TOTAL (SM_B + 3 * TILE_B)   // 62976

__device__ __forceinline__ void cp16(uint32_t dst, const void* src) {
    asm volatile("cp.async.cg.shared.global [%0], [%1], 16;" :: "r"(dst), "l"(src));
}

// 256 threads stage one 128x32-half tile (4 x 16B per row): 2 cp.async/thread.
__device__ __forceinline__ void stage_tile_h(const __half* __restrict__ src,
                                             int kt, uint32_t buf) {
    int tid = threadIdx.x;
    #pragma unroll
    for (int i = 0; i < 2; i++) {
        int idx = i * 256 + tid;          // 0..511
        int row = idx >> 2, c = idx & 3;  // 4 x 16B per row
        cp16(buf + (uint32_t)(row * (SPADH * 2) + c * 16),
             src + (size_t)row * H_ + kt * TK + c * 8);
    }
}

__global__ __launch_bounds__(256, 2) void k2_scores(
    const float* __restrict__ Va_w,
    const float* __restrict__ Va_b) {

    extern __shared__ char smem[];
    uint32_t sb = smem_u32(smem);
    float* sc_s = (float*)(smem + SM_SC);
    float* qv_s = (float*)(smem + SM_QV);
    float* va_s = (float*)(smem + SM_VA);

    int tid  = threadIdx.x;
    int wid  = tid >> 5;
    int lane = tid & 31;
    int wm   = wid >> 1;          // 0..3
    int wn   = wid & 1;           // 0..1
    int grp  = lane >> 2;         // 0..7
    int qid  = lane & 3;          // 0..3

    int blk = blockIdx.x;
    int b   = blk >> 4;
    int s0  = (blk & 15) * TM;
    const __half* keys_blk = g_keys_h + ((size_t)b * S_ + s0) * H_;

    if (tid < TM) sc_s[tid] = 0.f;

    float part[4] = {0.f, 0.f, 0.f, 0.f};

    for (int nt = 0; nt < H_ / TN; nt++) {
        __syncthreads();   // prev epilogue reads + prev-nt frag reads done
        if (tid < TN) {
            qv_s[tid] = g_qadd[b * H_ + nt * TN + tid];
            va_s[tid] = Va_w[nt * TN + tid];
        }
        const __half* Ua_nt = g_Ua_h + (size_t)(nt * TN) * H_;

        // 3-stage prologue: stage chunks 0,1
        stage_tile_h(keys_blk, 0, sb + SM_A);
        stage_tile_h(Ua_nt,    0, sb + SM_B);
        asm volatile("cp.async.commit_group;" ::: "memory");
        stage_tile_h(keys_blk, 1, sb + SM_A + TILE_B);
        stage_tile_h(Ua_nt,    1, sb + SM_B + TILE_B);
        asm volatile("cp.async.commit_group;" ::: "memory");

        float acc[2][8][4];
        #pragma unroll
        for (int mi = 0; mi < 2; mi++)
            #pragma unroll
            for (int ni = 0; ni < 8; ni++)
                #pragma unroll
                for (int c = 0; c < 4; c++)
                    acc[mi][ni][c] = 0.f;

        int cur = 0;   // rotating buffer index = kt % 3
        for (int kt = 0; kt < H_ / TK; kt++) {
            if (kt < H_ / TK - 1)
                asm volatile("cp.async.wait_group 1;" ::: "memory");
            else
                asm volatile("cp.async.wait_group 0;" ::: "memory");
            __syncthreads();   // chunk kt visible; prior reads of reused buf done

            if (kt + 2 < H_ / TK) {
                int nb = cur + 2; if (nb >= 3) nb -= 3;
                stage_tile_h(keys_blk, kt + 2, sb + SM_A + nb * TILE_B);
                stage_tile_h(Ua_nt,    kt + 2, sb + SM_B + nb * TILE_B);
                asm volatile("cp.async.commit_group;" ::: "memory");
            }

            const __half* a_s = (const __half*)(smem + SM_A + cur * TILE_B);
            const __half* b_s = (const __half*)(smem + SM_B + cur * TILE_B);

            #pragma unroll
            for (int k16 = 0; k16 < TK / 16; k16++) {
                int kb = k16 * 16 + 2 * qid;
                uint32_t af[2][4];
                uint32_t bf[8][2];
                #pragma unroll
                for (int mi = 0; mi < 2; mi++) {
                    int r = wm * 32 + mi * 16;
                    af[mi][0] = *(const uint32_t*)(a_s + (r + grp    ) * SPADH + kb    );
                    af[mi][1] = *(const uint32_t*)(a_s + (r + grp + 8) * SPADH + kb    );
                    af[mi][2] = *(const uint32_t*)(a_s + (r + grp    ) * SPADH + kb + 8);
                    af[mi][3] = *(const uint32_t*)(a_s + (r + grp + 8) * SPADH + kb + 8);
                }
                #pragma unroll
                for (int ni = 0; ni < 8; ni++) {
                    int n = wn * 64 + ni * 8;
                    bf[ni][0] = *(const uint32_t*)(b_s + (n + grp) * SPADH + kb    );
                    bf[ni][1] = *(const uint32_t*)(b_s + (n + grp) * SPADH + kb + 8);
                }
                #pragma unroll
                for (int mi = 0; mi < 2; mi++)
                    #pragma unroll
                    for (int ni = 0; ni < 8; ni++) {
                        asm volatile(
                            "mma.sync.aligned.m16n8k16.row.col.f32.f16.f16.f32 "
                            "{%0,%1,%2,%3}, {%4,%5,%6,%7}, {%8,%9}, {%0,%1,%2,%3};\n"
                            : "+f"(acc[mi][ni][0]), "+f"(acc[mi][ni][1]),
                              "+f"(acc[mi][ni][2]), "+f"(acc[mi][ni][3])
                            : "r"(af[mi][0]), "r"(af[mi][1]),
                              "r"(af[mi][2]), "r"(af[mi][3]),
                              "r"(bf[ni][0]), "r"(bf[ni][1]));
                    }
            }
            cur++; if (cur == 3) cur = 0;
        }

        // Epilogue: tanh + Va fold into per-row partials.
        #pragma unroll
        for (int ni = 0; ni < 8; ni++) {
            #pragma unroll
            for (int c = 0; c < 4; c++) {
                int gl = wn * 64 + ni * 8 + qid * 2 + (c & 1);
                float qv = qv_s[gl];
                float va = va_s[gl];
                #pragma unroll
                for (int mi = 0; mi < 2; mi++) {
                    float t = tanh_fast(qv + acc[mi][ni][c]);
                    part[mi * 2 + (c >> 1)] += va * t;
                }
            }
        }
    }

    // Reduce over the 4 lanes (qid) sharing each row.
    #pragma unroll
    for (int i = 0; i < 4; i++) {
        part[i] += __shfl_xor_sync(0xffffffffu, part[i], 1);
        part[i] += __shfl_xor_sync(0xffffffffu, part[i], 2);
    }
    if (qid == 0) {
        #pragma unroll
        for (int mi = 0; mi < 2; mi++)
            #pragma unroll
            for (int h = 0; h < 2; h++)
                atomicAdd(&sc_s[wm * 32 + mi * 16 + h * 8 + grp], part[mi * 2 + h]);
    }
    __syncthreads();
    if (tid < TM)
        g_scores[b * S_ + s0 + tid] = sc_s[tid] + Va_b[0];
}

// ---------------------------------------------------------------------------
// K3: softmax over S per batch row. grid=32, block=256 (8 elems/thread).
// ---------------------------------------------------------------------------
__global__ void k3_softmax(float* __restrict__ out_w) {
    int b = blockIdx.x;
    int tid = threadIdx.x;
    const float* sc = g_scores + b * S_;
    __shared__ float red_max[8];
    __shared__ float red_sum[8];

    float v[8];
    float lmax = -CUDART_INF_F;
    #pragma unroll
    for (int i = 0; i < 8; i++) {
        v[i] = sc[tid + i * 256];
        lmax = fmaxf(lmax, v[i]);
    }
    #pragma unroll
    for (int o = 16; o; o >>= 1)
        lmax = fmaxf(lmax, __shfl_xor_sync(0xffffffffu, lmax, o));
    if ((tid & 31) == 0) red_max[tid >> 5] = lmax;
    __syncthreads();
    float m = red_max[0];
    #pragma unroll
    for (int w = 1; w < 8; w++) m = fmaxf(m, red_max[w]);

    float lsum = 0.f;
    #pragma unroll
    for (int i = 0; i < 8; i++) {
        v[i] = __expf(v[i] - m);
        lsum += v[i];
    }
    #pragma unroll
    for (int o = 16; o; o >>= 1)
        lsum += __shfl_xor_sync(0xffffffffu, lsum, o);
    if ((tid & 31) == 0) red_sum[tid >> 5] = lsum;
    __syncthreads();
    float s = 0.f;
    #pragma unroll
    for (int w = 0; w < 8; w++) s += red_sum[w];
    float inv = 1.f / s;
    #pragma unroll
    for (int i = 0; i < 8; i++)
        out_w[b * S_ + tid + i * 256] = v[i] * inv;
}

// ---------------------------------------------------------------------------
// K4: split-S context partials, float4 columns (fp32 keys for accuracy).
// ---------------------------------------------------------------------------
__global__ void k4_context(const float* __restrict__ keys,
                           const float* __restrict__ w) {
    int bx = blockIdx.x;
    int b  = bx >> 4;
    int sc = bx & 15;

    __shared__ float w_s[128];
    if (threadIdx.x < 128)
        w_s[threadIdx.x] = w[b * S_ + sc * 128 + threadIdx.x];
    __syncthreads();

    const float4* kb = (const float4*)(keys + ((size_t)b * S_ + sc * 128) * H_) + threadIdx.x;
    float4 acc = make_float4(0.f, 0.f, 0.f, 0.f);
    #pragma unroll 8
    for (int s = 0; s < 128; s++) {
        float4 k4 = kb[(size_t)s * (H_ / 4)];
        float ws = w_s[s];
        acc.x += ws * k4.x;
        acc.y += ws * k4.y;
        acc.z += ws * k4.z;
        acc.w += ws * k4.w;
    }
    ((float4*)(g_ctxp + (size_t)sc * (B_ * H_) + b * H_))[threadIdx.x] = acc;
}

__global__ void k5_reduce(float* __restrict__ ctx) {
    int idx = blockIdx.x * 256 + threadIdx.x;
    float a = 0.f;
    #pragma unroll
    for (int p = 0; p < 16; p++)
        a += g_ctxp[p * (B_ * H_) + idx];
    ctx[idx] = a;
}

// ---------------------------------------------------------------------------
// Launch: d_out[0..32767] = context [32,1,1024]; d_out[32768..98303] = weights.
// ---------------------------------------------------------------------------
extern "C" void kernel_launch(void* const* d_in, const int* in_sizes, int n_in,
                              void* d_out, int out_size) {
    const float* query = (const float*)d_in[0];
    const float* keys  = (const float*)d_in[1];
    const float* Wa_w  = (const float*)d_in[2];
    const float* Wa_b  = (const float*)d_in[3];
    const float* Ua_w  = (const float*)d_in[4];
    const float* Ua_b  = (const float*)d_in[5];
    const float* Va_w  = (const float*)d_in[6];
    const float* Va_b  = (const float*)d_in[7];

    float* ctx  = (float*)d_out;
    float* wout = ctx + B_ * H_;

    static int init_done = 0;
    static __half* keys_h_p = nullptr;
    static __half* Ua_h_p = nullptr;
    if (!init_done) {
        cudaFuncSetAttribute(k2_scores, cudaFuncAttributeMaxDynamicSharedMemorySize, SM_TOTAL);
        cudaGetSymbolAddress((void**)&keys_h_p, g_keys_h);
        cudaGetSymbolAddress((void**)&Ua_h_p, g_Ua_h);
        init_done = 1;
    }

    k0_cvt<<<(B_ * S_ * H_) / (256 * 8), 256>>>(keys, keys_h_p);
    k0_cvt<<<(H_ * H_) / (256 * 8), 256>>>(Ua_w, Ua_h_p);
    k1_qproj<<<dim3(32, 8), 256>>>(query, Wa_w, Wa_b, Ua_b);
    k2_scores<<<(B_ * S_) / TM, 256, SM_TOTAL>>>(Va_w, Va_b);
    k3_softmax<<<B_, 256>>>(wout);
    k4_context<<<B_ * 16, 256>>>(keys, wout);
    k5_reduce<<<(B_ * H_) / 256, 256>>>(ctx);
}

// round 12
// speedup vs baseline: 2.5530x; 1.2174x over previous
#include <cuda_runtime.h>
#include <cuda_fp16.h>
#include <cstdint>
#include <math_constants.h>

#define B_ 32
#define S_ 2048
#define H_ 1024

// Scratch (no device allocation allowed)
__device__ float  g_qadd[B_ * H_];          // Wa_b + Ua_b + query @ Wa^T   [B,H]
__device__ float  g_scores[B_ * S_];        // pre-softmax scores           [B,S]
__device__ float  g_ctxp[16 * B_ * H_];     // K4 split-S partials
__device__ __half g_keys_h[B_ * S_ * H_];   // fp16 copy of keys (134 MB)
__device__ __half g_Ua_h[H_ * H_];          // fp16 copy of Ua   (2 MB)

__device__ __forceinline__ float tanh_fast(float x) {
    float y;
    asm("tanh.approx.f32 %0, %1;" : "=f"(y) : "f"(x));
    return y;
}

__device__ __forceinline__ uint32_t smem_u32(const void* p) {
    uint32_t a;
    asm("{ .reg .u64 t; cvta.to.shared.u64 t, %1; cvt.u32.u64 %0, t; }" : "=r"(a) : "l"(p));
    return a;
}

__device__ __forceinline__ void ldsm4(uint32_t& r0, uint32_t& r1, uint32_t& r2, uint32_t& r3,
                                      uint32_t addr) {
    asm volatile("ldmatrix.sync.aligned.m8n8.x4.shared.b16 {%0,%1,%2,%3}, [%4];"
                 : "=r"(r0), "=r"(r1), "=r"(r2), "=r"(r3) : "r"(addr));
}

// ---------------------------------------------------------------------------
// K0: fp32 -> fp16 conversion (8 elements / thread, 16B stores).
// ---------------------------------------------------------------------------
__global__ void k0_cvt(const float* __restrict__ src, __half* __restrict__ dst) {
    int i = (blockIdx.x * 256 + threadIdx.x) * 8;
    float4 f0 = *(const float4*)(src + i);
    float4 f1 = *(const float4*)(src + i + 4);
    __half2 h[4];
    h[0] = __floats2half2_rn(f0.x, f0.y);
    h[1] = __floats2half2_rn(f0.z, f0.w);
    h[2] = __floats2half2_rn(f1.x, f1.y);
    h[3] = __floats2half2_rn(f1.z, f1.w);
    *(uint4*)(dst + i) = *(uint4*)h;
}

// ---------------------------------------------------------------------------
// K1: qadd[b][g] = Wa_b[g] + Ua_b[g] + sum_h query[b][h] * Wa_w[g][h]
// ---------------------------------------------------------------------------
__global__ void k1_qproj(const float* __restrict__ query,
                         const float* __restrict__ Wa_w,
                         const float* __restrict__ Wa_b,
                         const float* __restrict__ Ua_b) {
    int b = blockIdx.x;
    int g0 = blockIdx.y * 128;
    __shared__ float q_s[H_];
    for (int i = threadIdx.x; i < H_; i += blockDim.x)
        q_s[i] = query[b * H_ + i];
    __syncthreads();

    int warp = threadIdx.x >> 5;
    int lane = threadIdx.x & 31;
    for (int gi = 0; gi < 16; gi++) {
        int g = g0 + warp * 16 + gi;
        const float* wrow = Wa_w + (size_t)g * H_;
        float acc = 0.f;
        #pragma unroll 8
        for (int h = lane; h < H_; h += 32)
            acc += q_s[h] * wrow[h];
        #pragma unroll
        for (int off = 16; off; off >>= 1)
            acc += __shfl_xor_sync(0xffffffffu, acc, off);
        if (lane == 0)
            g_qadd[b * H_ + g] = acc + Wa_b[g] + Ua_b[g];
    }
}

// ---------------------------------------------------------------------------
// K2: fused scores GEMM, mma.sync.m16n8k16.f16 + ldmatrix fragments
// (ldmatrix mapping verified by R9/R10 differential: identical outputs).
// CTA tile M=128 x N=128, TK=64 halves/chunk (4 k16 steps).
// FULL feature loop: nt = 0..7 covers all H=1024 features (R9/R10 bug: nt<2).
// 3-stage cp.async pipeline over GLOBAL chunk counter kc = nt*16 + kt
// (buffer = kc % 3, wait_group 1): staging lags compute by one chunk and
// flows across nt boundaries; epilogue hides next tile's staging.
// 8 warps: wm=wid>>1 (4 row strips of 32), wn=wid&1 (2 col strips of 64).
// Row pitch 72 halves (144 B): LDSM phase rows hit banks 4r mod 32, distinct.
// ---------------------------------------------------------------------------
#define TM 128
#define TN 128
#define TK 64                          // halves per k-chunk
#define NCHUNK (H_ / TK)               // 16 per nt
#define NT (H_ / TN)                   // 8 feature tiles
#define TOTC (NT * NCHUNK)             // 128 global chunks
#define SPADH 72                       // halves per row (144 B pitch)
#define TILE_B (TM * SPADH * 2)        // 18432 bytes per tile
// dynamic smem byte offsets
#define SM_SC  0                       // 128 floats
#define SM_QV  512                     // 128 floats
#define SM_VA  1024                    // 128 floats
#define SM_A   1536                    // 3 buffers x 18432
#define SM_B   (SM_A + 3 * TILE_B)
#define SM_TOTAL (SM_B + 3 * TILE_B)   // 112128

__device__ __forceinline__ void cp16(uint32_t dst, const void* src) {
    asm volatile("cp.async.cg.shared.global [%0], [%1], 16;" :: "r"(dst), "l"(src));
}

// 256 threads stage one 128x64-half tile (8 x 16B per row): 4 cp.async/thread.
__device__ __forceinline__ void stage_tile_h(const __half* __restrict__ src,
                                             int kt, uint32_t buf) {
    int tid = threadIdx.x;
    #pragma unroll
    for (int i = 0; i < 4; i++) {
        int idx = i * 256 + tid;          // 0..1023
        int row = idx >> 3, c = idx & 7;  // 8 x 16B per row
        cp16(buf + (uint32_t)(row * (SPADH * 2) + c * 16),
             src + (size_t)row * H_ + kt * TK + c * 8);
    }
}

// Stage global chunk kc: keys k-chunk (kc & 15), Ua feature-block (kc >> 4).
__device__ __forceinline__ void stage_chunk(const __half* __restrict__ keys_blk,
                                            int kc, uint32_t sb) {
    int nb  = kc % 3;
    int knt = kc >> 4;
    int kkt = kc & 15;
    stage_tile_h(keys_blk, kkt, sb + SM_A + nb * TILE_B);
    stage_tile_h(g_Ua_h + (size_t)(knt * TN) * H_, kkt, sb + SM_B + nb * TILE_B);
    asm volatile("cp.async.commit_group;" ::: "memory");
}

__global__ __launch_bounds__(256, 2) void k2_scores(
    const float* __restrict__ Va_w,
    const float* __restrict__ Va_b) {

    extern __shared__ char smem[];
    uint32_t sb = smem_u32(smem);
    float* sc_s = (float*)(smem + SM_SC);
    float* qv_s = (float*)(smem + SM_QV);
    float* va_s = (float*)(smem + SM_VA);

    int tid  = threadIdx.x;
    int wid  = tid >> 5;
    int lane = tid & 31;
    int wm   = wid >> 1;          // 0..3
    int wn   = wid & 1;           // 0..1
    int grp  = lane >> 2;         // 0..7
    int qid  = lane & 3;          // 0..3

    // ldmatrix per-lane address components (halves)
    int a_row  = (lane & 7) + ((lane >> 3) & 1) * 8;   // row within 16
    int a_koff = ((lane >> 4) & 1) * 8;                // k offset
    int b_n    = (lane & 7) + ((lane >> 4) & 1) * 8;   // n within 16
    int b_koff = ((lane >> 3) & 1) * 8;                // k offset

    int blk = blockIdx.x;
    int b   = blk >> 4;
    int s0  = (blk & 15) * TM;
    const __half* keys_blk = g_keys_h + ((size_t)b * S_ + s0) * H_;

    if (tid < TM) sc_s[tid] = 0.f;

    float part[4] = {0.f, 0.f, 0.f, 0.f};

    for (int nt = 0; nt < NT; nt++) {
        __syncthreads();   // prev epilogue reads done before qv_s/va_s rewrite
        if (tid < TN) {
            qv_s[tid] = g_qadd[b * H_ + nt * TN + tid];
            va_s[tid] = Va_w[nt * TN + tid];
        }

        if (nt == 0) {   // prologue: stage global chunks 0,1
            stage_chunk(keys_blk, 0, sb);
            stage_chunk(keys_blk, 1, sb);
        }
        // (later nt's first chunks are pre-staged by the global pipeline)

        float acc[2][8][4];
        #pragma unroll
        for (int mi = 0; mi < 2; mi++)
            #pragma unroll
            for (int ni = 0; ni < 8; ni++)
                #pragma unroll
                for (int c = 0; c < 4; c++)
                    acc[mi][ni][c] = 0.f;

        for (int kt = 0; kt < NCHUNK; kt++) {
            int kc  = nt * NCHUNK + kt;
            int cur = kc % 3;

            if (kc < TOTC - 1)
                asm volatile("cp.async.wait_group 1;" ::: "memory");
            else
                asm volatile("cp.async.wait_group 0;" ::: "memory");
            __syncthreads();   // chunk kc visible; reads of buf (kc+2)%3 done

            if (kc + 2 < TOTC)
                stage_chunk(keys_blk, kc + 2, sb);

            uint32_t aba = sb + SM_A + cur * TILE_B;
            uint32_t bba = sb + SM_B + cur * TILE_B;
            uint32_t aaddr[2], baddr[4];
            #pragma unroll
            for (int mi = 0; mi < 2; mi++)
                aaddr[mi] = aba + (uint32_t)(((wm * 32 + mi * 16 + a_row) * SPADH + a_koff) * 2);
            #pragma unroll
            for (int p = 0; p < 4; p++)
                baddr[p] = bba + (uint32_t)(((wn * 64 + p * 16 + b_n) * SPADH + b_koff) * 2);

            #pragma unroll
            for (int k16 = 0; k16 < TK / 16; k16++) {
                uint32_t kb = k16 * 32;   // bytes: 16 halves
                uint32_t af[2][4];
                uint32_t bf[8][2];
                #pragma unroll
                for (int mi = 0; mi < 2; mi++)
                    ldsm4(af[mi][0], af[mi][1], af[mi][2], af[mi][3], aaddr[mi] + kb);
                #pragma unroll
                for (int p = 0; p < 4; p++)
                    ldsm4(bf[2*p][0], bf[2*p][1], bf[2*p+1][0], bf[2*p+1][1], baddr[p] + kb);
                #pragma unroll
                for (int mi = 0; mi < 2; mi++)
                    #pragma unroll
                    for (int ni = 0; ni < 8; ni++) {
                        asm volatile(
                            "mma.sync.aligned.m16n8k16.row.col.f32.f16.f16.f32 "
                            "{%0,%1,%2,%3}, {%4,%5,%6,%7}, {%8,%9}, {%0,%1,%2,%3};\n"
                            : "+f"(acc[mi][ni][0]), "+f"(acc[mi][ni][1]),
                              "+f"(acc[mi][ni][2]), "+f"(acc[mi][ni][3])
                            : "r"(af[mi][0]), "r"(af[mi][1]),
                              "r"(af[mi][2]), "r"(af[mi][3]),
                              "r"(bf[ni][0]), "r"(bf[ni][1]));
                    }
            }
        }

        // Epilogue: tanh + Va fold into per-row partials (next chunks staging
        // in flight underneath).
        #pragma unroll
        for (int ni = 0; ni < 8; ni++) {
            #pragma unroll
            for (int c = 0; c < 4; c++) {
                int gl = wn * 64 + ni * 8 + qid * 2 + (c & 1);
                float qv = qv_s[gl];
                float va = va_s[gl];
                #pragma unroll
                for (int mi = 0; mi < 2; mi++) {
                    float t = tanh_fast(qv + acc[mi][ni][c]);
                    part[mi * 2 + (c >> 1)] += va * t;
                }
            }
        }
    }

    // Reduce over the 4 lanes (qid) sharing each row.
    #pragma unroll
    for (int i = 0; i < 4; i++) {
        part[i] += __shfl_xor_sync(0xffffffffu, part[i], 1);
        part[i] += __shfl_xor_sync(0xffffffffu, part[i], 2);
    }
    if (qid == 0) {
        #pragma unroll
        for (int mi = 0; mi < 2; mi++)
            #pragma unroll
            for (int h = 0; h < 2; h++)
                atomicAdd(&sc_s[wm * 32 + mi * 16 + h * 8 + grp], part[mi * 2 + h]);
    }
    __syncthreads();
    if (tid < TM)
        g_scores[b * S_ + s0 + tid] = sc_s[tid] + Va_b[0];
}

// ---------------------------------------------------------------------------
// K3: softmax over S per batch row. grid=32, block=256 (8 elems/thread).
// ---------------------------------------------------------------------------
__global__ void k3_softmax(float* __restrict__ out_w) {
    int b = blockIdx.x;
    int tid = threadIdx.x;
    const float* sc = g_scores + b * S_;
    __shared__ float red_max[8];
    __shared__ float red_sum[8];

    float v[8];
    float lmax = -CUDART_INF_F;
    #pragma unroll
    for (int i = 0; i < 8; i++) {
        v[i] = sc[tid + i * 256];
        lmax = fmaxf(lmax, v[i]);
    }
    #pragma unroll
    for (int o = 16; o; o >>= 1)
        lmax = fmaxf(lmax, __shfl_xor_sync(0xffffffffu, lmax, o));
    if ((tid & 31) == 0) red_max[tid >> 5] = lmax;
    __syncthreads();
    float m = red_max[0];
    #pragma unroll
    for (int w = 1; w < 8; w++) m = fmaxf(m, red_max[w]);

    float lsum = 0.f;
    #pragma unroll
    for (int i = 0; i < 8; i++) {
        v[i] = __expf(v[i] - m);
        lsum += v[i];
    }
    #pragma unroll
    for (int o = 16; o; o >>= 1)
        lsum += __shfl_xor_sync(0xffffffffu, lsum, o);
    if ((tid & 31) == 0) red_sum[tid >> 5] = lsum;
    __syncthreads();
    float s = 0.f;
    #pragma unroll
    for (int w = 0; w < 8; w++) s += red_sum[w];
    float inv = 1.f / s;
    #pragma unroll
    for (int i = 0; i < 8; i++)
        out_w[b * S_ + tid + i * 256] = v[i] * inv;
}

// ---------------------------------------------------------------------------
// K4: split-S context partials, float4 columns (fp32 keys for accuracy).
// ---------------------------------------------------------------------------
__global__ void k4_context(const float* __restrict__ keys,
                           const float* __restrict__ w) {
    int bx = blockIdx.x;
    int b  = bx >> 4;
    int sc = bx & 15;

    __shared__ float w_s[128];
    if (threadIdx.x < 128)
        w_s[threadIdx.x] = w[b * S_ + sc * 128 + threadIdx.x];
    __syncthreads();

    const float4* kb = (const float4*)(keys + ((size_t)b * S_ + sc * 128) * H_) + threadIdx.x;
    float4 acc = make_float4(0.f, 0.f, 0.f, 0.f);
    #pragma unroll 8
    for (int s = 0; s < 128; s++) {
        float4 k4 = kb[(size_t)s * (H_ / 4)];
        float ws = w_s[s];
        acc.x += ws * k4.x;
        acc.y += ws * k4.y;
        acc.z += ws * k4.z;
        acc.w += ws * k4.w;
    }
    ((float4*)(g_ctxp + (size_t)sc * (B_ * H_) + b * H_))[threadIdx.x] = acc;
}

__global__ void k5_reduce(float* __restrict__ ctx) {
    int idx = blockIdx.x * 256 + threadIdx.x;
    float a = 0.f;
    #pragma unroll
    for (int p = 0; p < 16; p++)
        a += g_ctxp[p * (B_ * H_) + idx];
    ctx[idx] = a;
}

// ---------------------------------------------------------------------------
// Launch: d_out[0..32767] = context [32,1,1024]; d_out[32768..98303] = weights.
// ---------------------------------------------------------------------------
extern "C" void kernel_launch(void* const* d_in, const int* in_sizes, int n_in,
                              void* d_out, int out_size) {
    const float* query = (const float*)d_in[0];
    const float* keys  = (const float*)d_in[1];
    const float* Wa_w  = (const float*)d_in[2];
    const float* Wa_b  = (const float*)d_in[3];
    const float* Ua_w  = (const float*)d_in[4];
    const float* Ua_b  = (const float*)d_in[5];
    const float* Va_w  = (const float*)d_in[6];
    const float* Va_b  = (const float*)d_in[7];

    float* ctx  = (float*)d_out;
    float* wout = ctx + B_ * H_;

    static int init_done = 0;
    static __half* keys_h_p = nullptr;
    static __half* Ua_h_p = nullptr;
    if (!init_done) {
        cudaFuncSetAttribute(k2_scores, cudaFuncAttributeMaxDynamicSharedMemorySize, SM_TOTAL);
        cudaGetSymbolAddress((void**)&keys_h_p, g_keys_h);
        cudaGetSymbolAddress((void**)&Ua_h_p, g_Ua_h);
        init_done = 1;
    }

    k0_cvt<<<(B_ * S_ * H_) / (256 * 8), 256>>>(keys, keys_h_p);
    k0_cvt<<<(H_ * H_) / (256 * 8), 256>>>(Ua_w, Ua_h_p);
    k1_qproj<<<dim3(32, 8), 256>>>(query, Wa_w, Wa_b, Ua_b);
    k2_scores<<<(B_ * S_) / TM, 256, SM_TOTAL>>>(Va_w, Va_b);
    k3_softmax<<<B_, 256>>>(wout);
    k4_context<<<B_ * 16, 256>>>(keys, wout);
    k5_reduce<<<(B_ * H_) / 256, 256>>>(ctx);
}

// round 13
// speedup vs baseline: 2.8476x; 1.1154x over previous
#include <cuda_runtime.h>
#include <cuda_fp16.h>
#include <cstdint>
#include <math_constants.h>

#define B_ 32
#define S_ 2048
#define H_ 1024

// Scratch (no device allocation allowed)
__device__ float  g_qadd[B_ * H_];          // Wa_b + Ua_b + query @ Wa^T   [B,H]
__device__ float  g_scores[B_ * S_];        // pre-softmax scores           [B,S]
__device__ float  g_ctxp[16 * B_ * H_];     // K4 split-S partials
__device__ __half g_keys_h[B_ * S_ * H_];   // fp16 copy of keys (134 MB)
__device__ __half g_Ua_h[H_ * H_];          // fp16 copy of Ua   (2 MB)

__device__ __forceinline__ float tanh_fast(float x) {
    float y;
    asm("tanh.approx.f32 %0, %1;" : "=f"(y) : "f"(x));
    return y;
}

__device__ __forceinline__ uint32_t smem_u32(const void* p) {
    uint32_t a;
    asm("{ .reg .u64 t; cvta.to.shared.u64 t, %1; cvt.u32.u64 %0, t; }" : "=r"(a) : "l"(p));
    return a;
}

__device__ __forceinline__ void ldsm4(uint32_t& r0, uint32_t& r1, uint32_t& r2, uint32_t& r3,
                                      uint32_t addr) {
    asm volatile("ldmatrix.sync.aligned.m8n8.x4.shared.b16 {%0,%1,%2,%3}, [%4];"
                 : "=r"(r0), "=r"(r1), "=r"(r2), "=r"(r3) : "r"(addr));
}

// ---------------------------------------------------------------------------
// K0: fp32 -> fp16 conversion (8 elements / thread, 16B stores).
// ---------------------------------------------------------------------------
__global__ void k0_cvt(const float* __restrict__ src, __half* __restrict__ dst) {
    int i = (blockIdx.x * 256 + threadIdx.x) * 8;
    float4 f0 = *(const float4*)(src + i);
    float4 f1 = *(const float4*)(src + i + 4);
    __half2 h[4];
    h[0] = __floats2half2_rn(f0.x, f0.y);
    h[1] = __floats2half2_rn(f0.z, f0.w);
    h[2] = __floats2half2_rn(f1.x, f1.y);
    h[3] = __floats2half2_rn(f1.z, f1.w);
    *(uint4*)(dst + i) = *(uint4*)h;
}

// ---------------------------------------------------------------------------
// K1: qadd[b][g] = Wa_b[g] + Ua_b[g] + sum_h query[b][h] * Wa_w[g][h]
// ---------------------------------------------------------------------------
__global__ void k1_qproj(const float* __restrict__ query,
                         const float* __restrict__ Wa_w,
                         const float* __restrict__ Wa_b,
                         const float* __restrict__ Ua_b) {
    int b = blockIdx.x;
    int g0 = blockIdx.y * 128;
    __shared__ float q_s[H_];
    for (int i = threadIdx.x; i < H_; i += blockDim.x)
        q_s[i] = query[b * H_ + i];
    __syncthreads();

    int warp = threadIdx.x >> 5;
    int lane = threadIdx.x & 31;
    for (int gi = 0; gi < 16; gi++) {
        int g = g0 + warp * 16 + gi;
        const float* wrow = Wa_w + (size_t)g * H_;
        float acc = 0.f;
        #pragma unroll 8
        for (int h = lane; h < H_; h += 32)
            acc += q_s[h] * wrow[h];
        #pragma unroll
        for (int off = 16; off; off >>= 1)
            acc += __shfl_xor_sync(0xffffffffu, acc, off);
        if (lane == 0)
            g_qadd[b * H_ + g] = acc + Wa_b[g] + Ua_b[g];
    }
}

// ---------------------------------------------------------------------------
// K2: fused scores GEMM, mma.sync.m16n8k16.f16 + ldmatrix (all verified).
// NEW SHAPE: CTA tile M=64 x N=128, 128 threads (4 warps, warp tile 32x64),
// 4 CTAs/SM (smem 55.5KB, <=128 regs). 4 independent CTAs cross-fill the
// tensor pipe during each other's barriers / LDSM bursts / epilogues —
// attacks the measured 48% tensor-idle at fixed 227us HMMA work.
// TK=64 halves/chunk, 2-stage cp.async pipeline over global chunk counter.
// Row pitch 72 halves (144 B): LDSM phase addresses conflict-free.
// ---------------------------------------------------------------------------
#define TM 64
#define TN 128
#define TK 64                          // halves per k-chunk
#define NCHUNK (H_ / TK)               // 16 per nt
#define NT (H_ / TN)                   // 8 feature tiles
#define TOTC (NT * NCHUNK)             // 128 global chunks
#define SPADH 72                       // halves per row (144 B pitch)
#define A_TILE_B (TM * SPADH * 2)      // 9216 bytes
#define B_TILE_B (TN * SPADH * 2)      // 18432 bytes
// dynamic smem byte offsets
#define SM_SC  0                       // 64 floats
#define SM_QV  256                     // 128 floats
#define SM_VA  768                     // 128 floats
#define SM_A   1536                    // 2 buffers x 9216
#define SM_B   (SM_A + 2 * A_TILE_B)   // 2 buffers x 18432
#define SM_TOTAL (SM_B + 2 * B_TILE_B) // 56832

__device__ __forceinline__ void cp16(uint32_t dst, const void* src) {
    asm volatile("cp.async.cg.shared.global [%0], [%1], 16;" :: "r"(dst), "l"(src));
}

// 128 threads stage A tile (64 rows x 8 x 16B): 4 cp.async/thread.
__device__ __forceinline__ void stage_A(const __half* __restrict__ src,
                                        int kt, uint32_t buf) {
    int tid = threadIdx.x;
    #pragma unroll
    for (int i = 0; i < 4; i++) {
        int idx = i * 128 + tid;          // 0..511
        int row = idx >> 3, c = idx & 7;
        cp16(buf + (uint32_t)(row * (SPADH * 2) + c * 16),
             src + (size_t)row * H_ + kt * TK + c * 8);
    }
}

// 128 threads stage B tile (128 rows x 8 x 16B): 8 cp.async/thread.
__device__ __forceinline__ void stage_B(const __half* __restrict__ src,
                                        int kt, uint32_t buf) {
    int tid = threadIdx.x;
    #pragma unroll
    for (int i = 0; i < 8; i++) {
        int idx = i * 128 + tid;          // 0..1023
        int row = idx >> 3, c = idx & 7;
        cp16(buf + (uint32_t)(row * (SPADH * 2) + c * 16),
             src + (size_t)row * H_ + kt * TK + c * 8);
    }
}

// Stage global chunk kc: keys k-chunk (kc & 15), Ua feature-block (kc >> 4).
__device__ __forceinline__ void stage_chunk(const __half* __restrict__ keys_blk,
                                            int kc, uint32_t sb) {
    int nb  = kc & 1;
    int knt = kc >> 4;
    int kkt = kc & 15;
    stage_A(keys_blk, kkt, sb + SM_A + nb * A_TILE_B);
    stage_B(g_Ua_h + (size_t)(knt * TN) * H_, kkt, sb + SM_B + nb * B_TILE_B);
    asm volatile("cp.async.commit_group;" ::: "memory");
}

__global__ __launch_bounds__(128, 4) void k2_scores(
    const float* __restrict__ Va_w,
    const float* __restrict__ Va_b) {

    extern __shared__ char smem[];
    uint32_t sb = smem_u32(smem);
    float* sc_s = (float*)(smem + SM_SC);
    float* qv_s = (float*)(smem + SM_QV);
    float* va_s = (float*)(smem + SM_VA);

    int tid  = threadIdx.x;
    int wid  = tid >> 5;
    int lane = tid & 31;
    int wm   = wid >> 1;          // 0..1 (32-row strips)
    int wn   = wid & 1;           // 0..1 (64-col strips)
    int grp  = lane >> 2;         // 0..7
    int qid  = lane & 3;          // 0..3

    // ldmatrix per-lane address components (halves)
    int a_row  = (lane & 7) + ((lane >> 3) & 1) * 8;   // row within 16
    int a_koff = ((lane >> 4) & 1) * 8;                // k offset
    int b_n    = (lane & 7) + ((lane >> 4) & 1) * 8;   // n within 16
    int b_koff = ((lane >> 3) & 1) * 8;                // k offset

    int blk = blockIdx.x;
    int b   = blk >> 5;                 // 32 s-tiles per batch
    int s0  = (blk & 31) * TM;
    const __half* keys_blk = g_keys_h + ((size_t)b * S_ + s0) * H_;

    if (tid < TM) sc_s[tid] = 0.f;

    float part[4] = {0.f, 0.f, 0.f, 0.f};

    for (int nt = 0; nt < NT; nt++) {
        __syncthreads();   // prev epilogue reads done before qv_s/va_s rewrite
        qv_s[tid] = g_qadd[b * H_ + nt * TN + tid];
        va_s[tid] = Va_w[nt * TN + tid];

        if (nt == 0)
            stage_chunk(keys_blk, 0, sb);   // prologue: stage global chunk 0

        float acc[2][8][4];
        #pragma unroll
        for (int mi = 0; mi < 2; mi++)
            #pragma unroll
            for (int ni = 0; ni < 8; ni++)
                #pragma unroll
                for (int c = 0; c < 4; c++)
                    acc[mi][ni][c] = 0.f;

        for (int kt = 0; kt < NCHUNK; kt++) {
            int kc  = nt * NCHUNK + kt;
            int cur = kc & 1;

            asm volatile("cp.async.wait_group 0;" ::: "memory");
            __syncthreads();   // chunk kc visible; reads of buf cur^1 done

            if (kc + 1 < TOTC)
                stage_chunk(keys_blk, kc + 1, sb);   // overlaps compute of kc

            uint32_t aba = sb + SM_A + cur * A_TILE_B;
            uint32_t bba = sb + SM_B + cur * B_TILE_B;
            uint32_t aaddr[2], baddr[4];
            #pragma unroll
            for (int mi = 0; mi < 2; mi++)
                aaddr[mi] = aba + (uint32_t)(((wm * 32 + mi * 16 + a_row) * SPADH + a_koff) * 2);
            #pragma unroll
            for (int p = 0; p < 4; p++)
                baddr[p] = bba + (uint32_t)(((wn * 64 + p * 16 + b_n) * SPADH + b_koff) * 2);

            #pragma unroll
            for (int k16 = 0; k16 < TK / 16; k16++) {
                uint32_t kb = k16 * 32;   // bytes: 16 halves
                uint32_t af[2][4];
                uint32_t bf[8][2];
                #pragma unroll
                for (int mi = 0; mi < 2; mi++)
                    ldsm4(af[mi][0], af[mi][1], af[mi][2], af[mi][3], aaddr[mi] + kb);
                #pragma unroll
                for (int p = 0; p < 4; p++)
                    ldsm4(bf[2*p][0], bf[2*p][1], bf[2*p+1][0], bf[2*p+1][1], baddr[p] + kb);
                #pragma unroll
                for (int mi = 0; mi < 2; mi++)
                    #pragma unroll
                    for (int ni = 0; ni < 8; ni++) {
                        asm volatile(
                            "mma.sync.aligned.m16n8k16.row.col.f32.f16.f16.f32 "
                            "{%0,%1,%2,%3}, {%4,%5,%6,%7}, {%8,%9}, {%0,%1,%2,%3};\n"
                            : "+f"(acc[mi][ni][0]), "+f"(acc[mi][ni][1]),
                              "+f"(acc[mi][ni][2]), "+f"(acc[mi][ni][3])
                            : "r"(af[mi][0]), "r"(af[mi][1]),
                              "r"(af[mi][2]), "r"(af[mi][3]),
                              "r"(bf[ni][0]), "r"(bf[ni][1]));
                    }
            }
        }

        // Epilogue: tanh + Va fold into per-row partials (next chunk staging
        // in flight; other CTAs on this SM fill the tensor pipe meanwhile).
        #pragma unroll
        for (int ni = 0; ni < 8; ni++) {
            #pragma unroll
            for (int c = 0; c < 4; c++) {
                int gl = wn * 64 + ni * 8 + qid * 2 + (c & 1);
                float qv = qv_s[gl];
                float va = va_s[gl];
                #pragma unroll
                for (int mi = 0; mi < 2; mi++) {
                    float t = tanh_fast(qv + acc[mi][ni][c]);
                    part[mi * 2 + (c >> 1)] += va * t;
                }
            }
        }
    }

    // Reduce over the 4 lanes (qid) sharing each row.
    #pragma unroll
    for (int i = 0; i < 4; i++) {
        part[i] += __shfl_xor_sync(0xffffffffu, part[i], 1);
        part[i] += __shfl_xor_sync(0xffffffffu, part[i], 2);
    }
    if (qid == 0) {
        #pragma unroll
        for (int mi = 0; mi < 2; mi++)
            #pragma unroll
            for (int h = 0; h < 2; h++)
                atomicAdd(&sc_s[wm * 32 + mi * 16 + h * 8 + grp], part[mi * 2 + h]);
    }
    __syncthreads();
    if (tid < TM)
        g_scores[b * S_ + s0 + tid] = sc_s[tid] + Va_b[0];
}

// ---------------------------------------------------------------------------
// K3: softmax over S per batch row. grid=32, block=256 (8 elems/thread).
// ---------------------------------------------------------------------------
__global__ void k3_softmax(float* __restrict__ out_w) {
    int b = blockIdx.x;
    int tid = threadIdx.x;
    const float* sc = g_scores + b * S_;
    __shared__ float red_max[8];
    __shared__ float red_sum[8];

    float v[8];
    float lmax = -CUDART_INF_F;
    #pragma unroll
    for (int i = 0; i < 8; i++) {
        v[i] = sc[tid + i * 256];
        lmax = fmaxf(lmax, v[i]);
    }
    #pragma unroll
    for (int o = 16; o; o >>= 1)
        lmax = fmaxf(lmax, __shfl_xor_sync(0xffffffffu, lmax, o));
    if ((tid & 31) == 0) red_max[tid >> 5] = lmax;
    __syncthreads();
    float m = red_max[0];
    #pragma unroll
    for (int w = 1; w < 8; w++) m = fmaxf(m, red_max[w]);

    float lsum = 0.f;
    #pragma unroll
    for (int i = 0; i < 8; i++) {
        v[i] = __expf(v[i] - m);
        lsum += v[i];
    }
    #pragma unroll
    for (int o = 16; o; o >>= 1)
        lsum += __shfl_xor_sync(0xffffffffu, lsum, o);
    if ((tid & 31) == 0) red_sum[tid >> 5] = lsum;
    __syncthreads();
    float s = 0.f;
    #pragma unroll
    for (int w = 0; w < 8; w++) s += red_sum[w];
    float inv = 1.f / s;
    #pragma unroll
    for (int i = 0; i < 8; i++)
        out_w[b * S_ + tid + i * 256] = v[i] * inv;
}

// ---------------------------------------------------------------------------
// K4: split-S context partials, float4 columns (fp32 keys for accuracy).
// ---------------------------------------------------------------------------
__global__ void k4_context(const float* __restrict__ keys,
                           const float* __restrict__ w) {
    int bx = blockIdx.x;
    int b  = bx >> 4;
    int sc = bx & 15;

    __shared__ float w_s[128];
    if (threadIdx.x < 128)
        w_s[threadIdx.x] = w[b * S_ + sc * 128 + threadIdx.x];
    __syncthreads();

    const float4* kb = (const float4*)(keys + ((size_t)b * S_ + sc * 128) * H_) + threadIdx.x;
    float4 acc = make_float4(0.f, 0.f, 0.f, 0.f);
    #pragma unroll 8
    for (int s = 0; s < 128; s++) {
        float4 k4 = kb[(size_t)s * (H_ / 4)];
        float ws = w_s[s];
        acc.x += ws * k4.x;
        acc.y += ws * k4.y;
        acc.z += ws * k4.z;
        acc.w += ws * k4.w;
    }
    ((float4*)(g_ctxp + (size_t)sc * (B_ * H_) + b * H_))[threadIdx.x] = acc;
}

__global__ void k5_reduce(float* __restrict__ ctx) {
    int idx = blockIdx.x * 256 + threadIdx.x;
    float a = 0.f;
    #pragma unroll
    for (int p = 0; p < 16; p++)
        a += g_ctxp[p * (B_ * H_) + idx];
    ctx[idx] = a;
}

// ---------------------------------------------------------------------------
// Launch: d_out[0..32767] = context [32,1,1024]; d_out[32768..98303] = weights.
// ---------------------------------------------------------------------------
extern "C" void kernel_launch(void* const* d_in, const int* in_sizes, int n_in,
                              void* d_out, int out_size) {
    const float* query = (const float*)d_in[0];
    const float* keys  = (const float*)d_in[1];
    const float* Wa_w  = (const float*)d_in[2];
    const float* Wa_b  = (const float*)d_in[3];
    const float* Ua_w  = (const float*)d_in[4];
    const float* Ua_b  = (const float*)d_in[5];
    const float* Va_w  = (const float*)d_in[6];
    const float* Va_b  = (const float*)d_in[7];

    float* ctx  = (float*)d_out;
    float* wout = ctx + B_ * H_;

    static int init_done = 0;
    static __half* keys_h_p = nullptr;
    static __half* Ua_h_p = nullptr;
    if (!init_done) {
        cudaFuncSetAttribute(k2_scores, cudaFuncAttributeMaxDynamicSharedMemorySize, SM_TOTAL);
        cudaGetSymbolAddress((void**)&keys_h_p, g_keys_h);
        cudaGetSymbolAddress((void**)&Ua_h_p, g_Ua_h);
        init_done = 1;
    }

    k0_cvt<<<(B_ * S_ * H_) / (256 * 8), 256>>>(keys, keys_h_p);
    k0_cvt<<<(H_ * H_) / (256 * 8), 256>>>(Ua_w, Ua_h_p);
    k1_qproj<<<dim3(32, 8), 256>>>(query, Wa_w, Wa_b, Ua_b);
    k2_scores<<<(B_ * S_) / TM, 128, SM_TOTAL>>>(Va_w, Va_b);
    k3_softmax<<<B_, 256>>>(wout);
    k4_context<<<B_ * 16, 256>>>(keys, wout);
    k5_reduce<<<(B_ * H_) / 256, 256>>>(ctx);
}